// round 1
// baseline (speedup 1.0000x reference)
#include <cuda_runtime.h>

#define CN0 262144
#define CN1 131072
#define CN2 65536
#define CE0 2097152
#define CE1 1048576
#define CIN 128
#define CH  32
#define CEPS 1e-12f

// ---- scratch (device globals; no allocations allowed) ----
__device__ float g_y0[(size_t)CN0 * CH];    // x @ wl0^T          (32 MB)
__device__ float g_r0[(size_t)CN1 * CH];    // x[:N1] @ wr0^T     (16 MB)
__device__ float g_agg0[(size_t)CN1 * CH];  // scatter accumulator
__device__ float g_cnt0[CN1];
__device__ float g_h[(size_t)CN1 * CH];     // layer-0 output
__device__ float g_z1[(size_t)CN1 * CH];    // h @ wl1^T
__device__ float g_r1[(size_t)CN2 * CH];    // h[:N2] @ wr1^T
__device__ float g_agg1[(size_t)CN2 * CH];
__device__ float g_cnt1[CN2];

// ============================================================
// proj0: per-warp 4 rows. y0 = x@wl0^T (+ optionally r0 = x@wr0^T,
// zero agg0/cnt0). Weights staged transposed in smem (conflict-free).
// ============================================================
template <bool DO_R>
__global__ __launch_bounds__(256) void proj0_kernel(
    const float* __restrict__ x,
    const float* __restrict__ wl0,
    const float* __restrict__ wr0,
    int row_base)
{
    __shared__ float swl[CIN * CH];   // [k][j]
    __shared__ float swr[CIN * CH];
    int tid = threadIdx.x;
    #pragma unroll
    for (int idx = tid; idx < CIN * CH; idx += 256) {
        int j = idx >> 7, k = idx & 127;
        swl[k * CH + j] = wl0[idx];
        if (DO_R) swr[k * CH + j] = wr0[idx];
    }
    __syncthreads();

    int lane = tid & 31;
    int warp = blockIdx.x * 8 + (tid >> 5);
    int rb = row_base + warp * 4;

    const float4* x4 = (const float4*)x;
    size_t b0 = (size_t)rb * 32;   // float4 index of row rb

    float al[4] = {0.f, 0.f, 0.f, 0.f};
    float ar[4] = {0.f, 0.f, 0.f, 0.f};

    #pragma unroll 4
    for (int k4 = 0; k4 < 32; k4++) {
        float4 v[4];
        #pragma unroll
        for (int i = 0; i < 4; i++) v[i] = __ldg(&x4[b0 + (size_t)i * 32 + k4]);
        int kb = k4 * 4;
        float wlr[4], wrr[4];
        #pragma unroll
        for (int d = 0; d < 4; d++) {
            wlr[d] = swl[(kb + d) * CH + lane];
            if (DO_R) wrr[d] = swr[(kb + d) * CH + lane];
        }
        #pragma unroll
        for (int i = 0; i < 4; i++) {
            al[i] = fmaf(v[i].x, wlr[0], al[i]);
            al[i] = fmaf(v[i].y, wlr[1], al[i]);
            al[i] = fmaf(v[i].z, wlr[2], al[i]);
            al[i] = fmaf(v[i].w, wlr[3], al[i]);
            if (DO_R) {
                ar[i] = fmaf(v[i].x, wrr[0], ar[i]);
                ar[i] = fmaf(v[i].y, wrr[1], ar[i]);
                ar[i] = fmaf(v[i].z, wrr[2], ar[i]);
                ar[i] = fmaf(v[i].w, wrr[3], ar[i]);
            }
        }
    }

    #pragma unroll
    for (int i = 0; i < 4; i++) {
        int r = rb + i;
        g_y0[(size_t)r * CH + lane] = al[i];
        if (DO_R) {
            g_r0[(size_t)r * CH + lane] = ar[i];
            g_agg0[(size_t)r * CH + lane] = 0.f;
            if (lane == 0) g_cnt0[r] = 0.f;
        }
    }
}

// ============================================================
// scatter0: warp handles 4 edges; lane = feature. Atomic add into agg0.
// ============================================================
__global__ __launch_bounds__(256) void scatter0_kernel(
    const int* __restrict__ src, const int* __restrict__ tgt)
{
    int lane = threadIdx.x & 31;
    int warp = blockIdx.x * 8 + (threadIdx.x >> 5);
    int e0 = warp * 4;

    int s0 = __ldg(src + e0 + 0), s1 = __ldg(src + e0 + 1);
    int s2 = __ldg(src + e0 + 2), s3 = __ldg(src + e0 + 3);
    int t0 = __ldg(tgt + e0 + 0), t1 = __ldg(tgt + e0 + 1);
    int t2 = __ldg(tgt + e0 + 2), t3 = __ldg(tgt + e0 + 3);

    float v0 = g_y0[(size_t)s0 * CH + lane];
    float v1 = g_y0[(size_t)s1 * CH + lane];
    float v2 = g_y0[(size_t)s2 * CH + lane];
    float v3 = g_y0[(size_t)s3 * CH + lane];

    atomicAdd(&g_agg0[(size_t)t0 * CH + lane], v0);
    atomicAdd(&g_agg0[(size_t)t1 * CH + lane], v1);
    atomicAdd(&g_agg0[(size_t)t2 * CH + lane], v2);
    atomicAdd(&g_agg0[(size_t)t3 * CH + lane], v3);
    if (lane == 0) {
        atomicAdd(&g_cnt0[t0], 1.f);
        atomicAdd(&g_cnt0[t1], 1.f);
        atomicAdd(&g_cnt0[t2], 1.f);
        atomicAdd(&g_cnt0[t3], 1.f);
    }
}

// ============================================================
// finalize0: h = relu(l2norm(agg0/cnt + bl0 + r0)). Warp per row.
// ============================================================
__global__ __launch_bounds__(256) void finalize0_kernel(const float* __restrict__ bl0)
{
    int lane = threadIdx.x & 31;
    int row = blockIdx.x * 8 + (threadIdx.x >> 5);
    float c = fmaxf(g_cnt0[row], 1.f);
    float v = g_agg0[(size_t)row * CH + lane] / c + bl0[lane]
            + g_r0[(size_t)row * CH + lane];
    float s = v * v;
    #pragma unroll
    for (int o = 16; o; o >>= 1) s += __shfl_xor_sync(0xffffffffu, s, o);
    float nrm = fmaxf(sqrtf(s), CEPS);
    v = fmaxf(v / nrm, 0.f);
    g_h[(size_t)row * CH + lane] = v;
}

// ============================================================
// proj1: z1 = h@wl1^T (all N1), r1 = h[:N2]@wr1^T, zero agg1/cnt1.
// ============================================================
__global__ __launch_bounds__(256) void proj1_kernel(
    const float* __restrict__ wl1, const float* __restrict__ wr1)
{
    __shared__ float swl[CH * CH];
    __shared__ float swr[CH * CH];
    int tid = threadIdx.x;
    for (int idx = tid; idx < CH * CH; idx += 256) {
        int j = idx >> 5, k = idx & 31;
        swl[k * CH + j] = wl1[idx];
        swr[k * CH + j] = wr1[idx];
    }
    __syncthreads();

    int lane = tid & 31;
    int warp = blockIdx.x * 8 + (tid >> 5);
    int rb = warp * 4;

    const float4* h4 = (const float4*)g_h;
    size_t b0 = (size_t)rb * 8;

    float al[4] = {0.f, 0.f, 0.f, 0.f};
    float ar[4] = {0.f, 0.f, 0.f, 0.f};

    #pragma unroll
    for (int k4 = 0; k4 < 8; k4++) {
        float4 v[4];
        #pragma unroll
        for (int i = 0; i < 4; i++) v[i] = h4[b0 + (size_t)i * 8 + k4];
        int kb = k4 * 4;
        float wlr[4], wrr[4];
        #pragma unroll
        for (int d = 0; d < 4; d++) {
            wlr[d] = swl[(kb + d) * CH + lane];
            wrr[d] = swr[(kb + d) * CH + lane];
        }
        #pragma unroll
        for (int i = 0; i < 4; i++) {
            al[i] = fmaf(v[i].x, wlr[0], al[i]);
            al[i] = fmaf(v[i].y, wlr[1], al[i]);
            al[i] = fmaf(v[i].z, wlr[2], al[i]);
            al[i] = fmaf(v[i].w, wlr[3], al[i]);
            ar[i] = fmaf(v[i].x, wrr[0], ar[i]);
            ar[i] = fmaf(v[i].y, wrr[1], ar[i]);
            ar[i] = fmaf(v[i].z, wrr[2], ar[i]);
            ar[i] = fmaf(v[i].w, wrr[3], ar[i]);
        }
    }

    #pragma unroll
    for (int i = 0; i < 4; i++) {
        int r = rb + i;
        g_z1[(size_t)r * CH + lane] = al[i];
        if (r < CN2) {
            g_r1[(size_t)r * CH + lane] = ar[i];
            g_agg1[(size_t)r * CH + lane] = 0.f;
            if (lane == 0) g_cnt1[r] = 0.f;
        }
    }
}

// ============================================================
// scatter1
// ============================================================
__global__ __launch_bounds__(256) void scatter1_kernel(
    const int* __restrict__ src, const int* __restrict__ tgt)
{
    int lane = threadIdx.x & 31;
    int warp = blockIdx.x * 8 + (threadIdx.x >> 5);
    int e0 = warp * 4;

    int s0 = __ldg(src + e0 + 0), s1 = __ldg(src + e0 + 1);
    int s2 = __ldg(src + e0 + 2), s3 = __ldg(src + e0 + 3);
    int t0 = __ldg(tgt + e0 + 0), t1 = __ldg(tgt + e0 + 1);
    int t2 = __ldg(tgt + e0 + 2), t3 = __ldg(tgt + e0 + 3);

    float v0 = g_z1[(size_t)s0 * CH + lane];
    float v1 = g_z1[(size_t)s1 * CH + lane];
    float v2 = g_z1[(size_t)s2 * CH + lane];
    float v3 = g_z1[(size_t)s3 * CH + lane];

    atomicAdd(&g_agg1[(size_t)t0 * CH + lane], v0);
    atomicAdd(&g_agg1[(size_t)t1 * CH + lane], v1);
    atomicAdd(&g_agg1[(size_t)t2 * CH + lane], v2);
    atomicAdd(&g_agg1[(size_t)t3 * CH + lane], v3);
    if (lane == 0) {
        atomicAdd(&g_cnt1[t0], 1.f);
        atomicAdd(&g_cnt1[t1], 1.f);
        atomicAdd(&g_cnt1[t2], 1.f);
        atomicAdd(&g_cnt1[t3], 1.f);
    }
}

// ============================================================
// finalize1: out = l2norm(agg1/cnt + bl1 + r1)  (no relu)
// ============================================================
__global__ __launch_bounds__(256) void finalize1_kernel(
    const float* __restrict__ bl1, float* __restrict__ out)
{
    int lane = threadIdx.x & 31;
    int row = blockIdx.x * 8 + (threadIdx.x >> 5);
    float c = fmaxf(g_cnt1[row], 1.f);
    float v = g_agg1[(size_t)row * CH + lane] / c + bl1[lane]
            + g_r1[(size_t)row * CH + lane];
    float s = v * v;
    #pragma unroll
    for (int o = 16; o; o >>= 1) s += __shfl_xor_sync(0xffffffffu, s, o);
    float nrm = fmaxf(sqrtf(s), CEPS);
    out[(size_t)row * CH + lane] = v / nrm;
}

// ============================================================
extern "C" void kernel_launch(void* const* d_in, const int* in_sizes, int n_in,
                              void* d_out, int out_size)
{
    const float* x    = (const float*)d_in[0];
    const int*   src0 = (const int*)d_in[1];
    const int*   tgt0 = (const int*)d_in[2];
    const int*   src1 = (const int*)d_in[3];
    const int*   tgt1 = (const int*)d_in[4];
    const float* wl0  = (const float*)d_in[5];
    const float* bl0  = (const float*)d_in[6];
    const float* wr0  = (const float*)d_in[7];
    const float* wl1  = (const float*)d_in[8];
    const float* bl1  = (const float*)d_in[9];
    const float* wr1  = (const float*)d_in[10];
    float* out = (float*)d_out;

    // layer 0
    proj0_kernel<true ><<<CN1 / 32, 256>>>(x, wl0, wr0, 0);           // rows [0, N1): y0 + r0 + zero agg
    proj0_kernel<false><<<(CN0 - CN1) / 32, 256>>>(x, wl0, wr0, CN1); // rows [N1, N0): y0 only
    scatter0_kernel<<<CE0 / 32, 256>>>(src0, tgt0);
    finalize0_kernel<<<CN1 / 8, 256>>>(bl0);

    // layer 1
    proj1_kernel<<<CN1 / 32, 256>>>(wl1, wr1);
    scatter1_kernel<<<CE1 / 32, 256>>>(src1, tgt1);
    finalize1_kernel<<<CN2 / 8, 256>>>(bl1, out);
}

// round 3
// speedup vs baseline: 1.0836x; 1.0836x over previous
#include <cuda_runtime.h>

#define CN0 262144
#define CN1 131072
#define CN2 65536
#define CE0 2097152
#define CE1 1048576
#define CIN 128
#define CH  32
#define CEPS 1e-12f

// ---- scratch (device globals; referenced from DEVICE code only) ----
__device__ float g_y0[(size_t)CN0 * CH];    // x @ wl0^T          (32 MB)
__device__ float g_r0[(size_t)CN1 * CH];    // x[:N1] @ wr0^T     (16 MB)
__device__ float g_agg0[(size_t)CN1 * CH];  // scatter accumulator
__device__ float g_cnt0[CN1];
__device__ float g_h[(size_t)CN1 * CH];     // layer-0 output
__device__ float g_z1[(size_t)CN1 * CH];    // h @ wl1^T
__device__ float g_r1[(size_t)CN2 * CH];    // h[:N2] @ wr1^T
__device__ float g_agg1[(size_t)CN2 * CH];
__device__ float g_cnt1[CN2];

__device__ __forceinline__ void red_add_v4(float* p, float4 v) {
    asm volatile("red.global.add.v4.f32 [%0], {%1,%2,%3,%4};"
                 :: "l"(p), "f"(v.x), "f"(v.y), "f"(v.z), "f"(v.w) : "memory");
}
__device__ __forceinline__ void red_add_f32(float* p, float v) {
    asm volatile("red.global.add.f32 [%0], %1;" :: "l"(p), "f"(v) : "memory");
}

// ============================================================
// proj0: per-warp 4 rows. y0 = x@wl0^T (+ optionally r0 = x@wr0^T,
// zero agg0/cnt0). Weights staged transposed in smem (conflict-free).
// ============================================================
template <bool DO_R>
__global__ __launch_bounds__(256) void proj0_kernel(
    const float* __restrict__ x,
    const float* __restrict__ wl0,
    const float* __restrict__ wr0,
    int row_base)
{
    __shared__ float swl[CIN * CH];   // [k][j]
    __shared__ float swr[CIN * CH];
    int tid = threadIdx.x;
    #pragma unroll
    for (int idx = tid; idx < CIN * CH; idx += 256) {
        int j = idx >> 7, k = idx & 127;
        swl[k * CH + j] = wl0[idx];
        if (DO_R) swr[k * CH + j] = wr0[idx];
    }
    __syncthreads();

    int lane = tid & 31;
    int warp = blockIdx.x * 8 + (tid >> 5);
    int rb = row_base + warp * 4;

    const float4* x4 = (const float4*)x;
    size_t b0 = (size_t)rb * 32;   // float4 index of row rb

    float al[4] = {0.f, 0.f, 0.f, 0.f};
    float ar[4] = {0.f, 0.f, 0.f, 0.f};

    #pragma unroll 4
    for (int k4 = 0; k4 < 32; k4++) {
        float4 v[4];
        #pragma unroll
        for (int i = 0; i < 4; i++) v[i] = __ldg(&x4[b0 + (size_t)i * 32 + k4]);
        int kb = k4 * 4;
        float wlr[4], wrr[4];
        #pragma unroll
        for (int d = 0; d < 4; d++) {
            wlr[d] = swl[(kb + d) * CH + lane];
            if (DO_R) wrr[d] = swr[(kb + d) * CH + lane];
        }
        #pragma unroll
        for (int i = 0; i < 4; i++) {
            al[i] = fmaf(v[i].x, wlr[0], al[i]);
            al[i] = fmaf(v[i].y, wlr[1], al[i]);
            al[i] = fmaf(v[i].z, wlr[2], al[i]);
            al[i] = fmaf(v[i].w, wlr[3], al[i]);
            if (DO_R) {
                ar[i] = fmaf(v[i].x, wrr[0], ar[i]);
                ar[i] = fmaf(v[i].y, wrr[1], ar[i]);
                ar[i] = fmaf(v[i].z, wrr[2], ar[i]);
                ar[i] = fmaf(v[i].w, wrr[3], ar[i]);
            }
        }
    }

    #pragma unroll
    for (int i = 0; i < 4; i++) {
        int r = rb + i;
        g_y0[(size_t)r * CH + lane] = al[i];
        if (DO_R) {
            g_r0[(size_t)r * CH + lane] = ar[i];
            g_agg0[(size_t)r * CH + lane] = 0.f;
            if (lane == 0) g_cnt0[r] = 0.f;
        }
    }
}

// ============================================================
// scatter: 8 lanes per edge, float4 gather + red.global.add.v4.
// LAYER selects device-global buffers internally (no host symbol refs).
// ============================================================
template <int LAYER, int EPW>
__global__ __launch_bounds__(256) void scatter_kernel(
    const int* __restrict__ src, const int* __restrict__ tgt)
{
    const float* table = (LAYER == 0) ? g_y0  : g_z1;
    float*       agg   = (LAYER == 0) ? g_agg0 : g_agg1;
    float*       cnt   = (LAYER == 0) ? g_cnt0 : g_cnt1;

    int lane = threadIdx.x & 31;
    int warp = blockIdx.x * 8 + (threadIdx.x >> 5);
    int e_base = warp * EPW;
    int q = lane >> 3;            // which of 4 edges in this iteration
    int f4 = lane & 7;            // float4 slot within the 32-feature row
    bool is_cnt = (f4 == 0);

    #pragma unroll
    for (int j = 0; j < EPW; j += 4) {
        int e = e_base + j + q;
        int s = __ldg(src + e);
        int t = __ldg(tgt + e);
        float4 v = __ldg((const float4*)(table + (size_t)s * CH) + f4);
        red_add_v4(agg + (size_t)t * CH + f4 * 4, v);
        if (is_cnt) red_add_f32(cnt + t, 1.f);
    }
}

// ============================================================
// finalize: 8 threads per row, float4 per thread.
// LAYER 0: h = relu(l2norm(agg0/cnt0 + bl0 + r0)) -> g_h
// LAYER 1: out = l2norm(agg1/cnt1 + bl1 + r1)     -> d_out param
// ============================================================
template <int LAYER>
__global__ __launch_bounds__(256) void finalize_kernel(
    const float* __restrict__ bias, float* __restrict__ out_param)
{
    const float* agg = (LAYER == 0) ? g_agg0 : g_agg1;
    const float* cnt = (LAYER == 0) ? g_cnt0 : g_cnt1;
    const float* rt  = (LAYER == 0) ? g_r0   : g_r1;
    float*       out = (LAYER == 0) ? g_h    : out_param;

    int tid = blockIdx.x * 256 + threadIdx.x;
    int row = tid >> 3;
    int f4 = tid & 7;

    float c = fmaxf(__ldg(cnt + row), 1.f);
    float inv = 1.f / c;
    float4 a = __ldg((const float4*)(agg + (size_t)row * CH) + f4);
    float4 b = __ldg((const float4*)bias + f4);
    float4 r = __ldg((const float4*)(rt + (size_t)row * CH) + f4);

    float4 v;
    v.x = fmaf(a.x, inv, b.x) + r.x;
    v.y = fmaf(a.y, inv, b.y) + r.y;
    v.z = fmaf(a.z, inv, b.z) + r.z;
    v.w = fmaf(a.w, inv, b.w) + r.w;

    float s = v.x * v.x + v.y * v.y + v.z * v.z + v.w * v.w;
    s += __shfl_xor_sync(0xffffffffu, s, 1);
    s += __shfl_xor_sync(0xffffffffu, s, 2);
    s += __shfl_xor_sync(0xffffffffu, s, 4);
    float rinv = 1.f / fmaxf(sqrtf(s), CEPS);

    float4 o;
    o.x = v.x * rinv; o.y = v.y * rinv; o.z = v.z * rinv; o.w = v.w * rinv;
    if (LAYER == 0) {
        o.x = fmaxf(o.x, 0.f); o.y = fmaxf(o.y, 0.f);
        o.z = fmaxf(o.z, 0.f); o.w = fmaxf(o.w, 0.f);
    }
    ((float4*)(out + (size_t)row * CH))[f4] = o;
}

// ============================================================
// proj1: z1 = h@wl1^T (all N1), r1 = h[:N2]@wr1^T, zero agg1/cnt1.
// ============================================================
__global__ __launch_bounds__(256) void proj1_kernel(
    const float* __restrict__ wl1, const float* __restrict__ wr1)
{
    __shared__ float swl[CH * CH];
    __shared__ float swr[CH * CH];
    int tid = threadIdx.x;
    for (int idx = tid; idx < CH * CH; idx += 256) {
        int j = idx >> 5, k = idx & 31;
        swl[k * CH + j] = wl1[idx];
        swr[k * CH + j] = wr1[idx];
    }
    __syncthreads();

    int lane = tid & 31;
    int warp = blockIdx.x * 8 + (tid >> 5);
    int rb = warp * 4;

    const float4* h4 = (const float4*)g_h;
    size_t b0 = (size_t)rb * 8;

    float al[4] = {0.f, 0.f, 0.f, 0.f};
    float ar[4] = {0.f, 0.f, 0.f, 0.f};

    #pragma unroll
    for (int k4 = 0; k4 < 8; k4++) {
        float4 v[4];
        #pragma unroll
        for (int i = 0; i < 4; i++) v[i] = h4[b0 + (size_t)i * 8 + k4];
        int kb = k4 * 4;
        float wlr[4], wrr[4];
        #pragma unroll
        for (int d = 0; d < 4; d++) {
            wlr[d] = swl[(kb + d) * CH + lane];
            wrr[d] = swr[(kb + d) * CH + lane];
        }
        #pragma unroll
        for (int i = 0; i < 4; i++) {
            al[i] = fmaf(v[i].x, wlr[0], al[i]);
            al[i] = fmaf(v[i].y, wlr[1], al[i]);
            al[i] = fmaf(v[i].z, wlr[2], al[i]);
            al[i] = fmaf(v[i].w, wlr[3], al[i]);
            ar[i] = fmaf(v[i].x, wrr[0], ar[i]);
            ar[i] = fmaf(v[i].y, wrr[1], ar[i]);
            ar[i] = fmaf(v[i].z, wrr[2], ar[i]);
            ar[i] = fmaf(v[i].w, wrr[3], ar[i]);
        }
    }

    #pragma unroll
    for (int i = 0; i < 4; i++) {
        int r = rb + i;
        g_z1[(size_t)r * CH + lane] = al[i];
        if (r < CN2) {
            g_r1[(size_t)r * CH + lane] = ar[i];
            g_agg1[(size_t)r * CH + lane] = 0.f;
            if (lane == 0) g_cnt1[r] = 0.f;
        }
    }
}

// ============================================================
extern "C" void kernel_launch(void* const* d_in, const int* in_sizes, int n_in,
                              void* d_out, int out_size)
{
    const float* x    = (const float*)d_in[0];
    const int*   src0 = (const int*)d_in[1];
    const int*   tgt0 = (const int*)d_in[2];
    const int*   src1 = (const int*)d_in[3];
    const int*   tgt1 = (const int*)d_in[4];
    const float* wl0  = (const float*)d_in[5];
    const float* bl0  = (const float*)d_in[6];
    const float* wr0  = (const float*)d_in[7];
    const float* wl1  = (const float*)d_in[8];
    const float* bl1  = (const float*)d_in[9];
    const float* wr1  = (const float*)d_in[10];
    float* out = (float*)d_out;

    // layer 0
    proj0_kernel<true ><<<CN1 / 32, 256>>>(x, wl0, wr0, 0);
    proj0_kernel<false><<<(CN0 - CN1) / 32, 256>>>(x, wl0, wr0, CN1);
    scatter_kernel<0, 32><<<CE0 / 256, 256>>>(src0, tgt0);
    finalize_kernel<0><<<CN1 * 8 / 256, 256>>>(bl0, nullptr);

    // layer 1
    proj1_kernel<<<CN1 / 32, 256>>>(wl1, wr1);
    scatter_kernel<1, 32><<<CE1 / 256, 256>>>(src1, tgt1);
    finalize_kernel<1><<<CN2 * 8 / 256, 256>>>(bl1, out);
}